// round 7
// baseline (speedup 1.0000x reference)
#include <cuda_runtime.h>
#include <math.h>

#define NMAX 50000
#define EMAX 800000
#define ELLW 64   // padded ELL width (max in-degree; Poisson(16) -> P(>=64) ~ 0)

typedef unsigned long long ull;

// ---------------- scratch (static device globals; no allocation) ----------------
__device__ float g_m1  [NMAX * 128];
__device__ float g_q1  [NMAX * 128];
__device__ float g_p1  [NMAX * 128];
__device__ float g_agg1[NMAX * 128];
__device__ float g_q2  [NMAX * 64];
__device__ float g_p2  [NMAX * 64];
__device__ int   g_cur [NMAX];
__device__ int   g_ell [NMAX * ELLW];
__device__ ull   g_wd  [4 * 128 * 128];   // pre-duplicated f32x2 weights: W0|Wq1|Wp1|[Wq2:Wp2]

__device__ __forceinline__ float gelu_erf(float x) {
    return 0.5f * x * (1.0f + erff(x * 0.7071067811865476f));
}

// packed fp32x2 helpers (sm_100+)
__device__ __forceinline__ ull ffma2(ull a, ull b, ull c) {
    ull d;
    asm("fma.rn.f32x2 %0, %1, %2, %3;" : "=l"(d) : "l"(a), "l"(b), "l"(c));
    return d;
}
__device__ __forceinline__ ull add2(ull a, ull b) {
    ull d;
    asm("add.rn.f32x2 %0, %1, %2;" : "=l"(d) : "l"(a), "l"(b));
    return d;
}
__device__ __forceinline__ ull dup2(float w) {
    ull d;
    asm("mov.b64 %0, {%1, %1};" : "=l"(d) : "f"(w));
    return d;
}
__device__ __forceinline__ ull pack2(float lo, float hi) {
    ull d;
    asm("mov.b64 %0, {%1, %2};" : "=l"(d) : "f"(lo), "f"(hi));
    return d;
}
__device__ __forceinline__ void unpack2(ull v, float& lo, float& hi) {
    asm("mov.b64 {%0, %1}, %2;" : "=f"(lo), "=f"(hi) : "l"(v));
}
__device__ __forceinline__ float ex2f(float x) {
    float r;
    asm("ex2.approx.ftz.f32 %0, %1;" : "=f"(r) : "f"(x));
    return r;
}

// ---------------- weight prepack: dup every weight into {w,w} f32x2 ----------------
__global__ void prep_w_k(const float* __restrict__ W0,
                         const float* __restrict__ Wq1, const float* __restrict__ Wp1,
                         const float* __restrict__ Wq2, const float* __restrict__ Wp2,
                         ull* __restrict__ wd)
{
    const int i = blockIdx.x * blockDim.x + threadIdx.x;   // 0..65535
    const int mat = i >> 14;
    const int idx = i & 16383;
    const int k = idx >> 7, c = idx & 127;
    float v;
    if      (mat == 0) v = W0 [k * 128 + c];
    else if (mat == 1) v = Wq1[k * 128 + c];
    else if (mat == 2) v = Wp1[k * 128 + c];
    else               v = (c < 64) ? Wq2[k * 64 + c] : Wp2[k * 64 + c - 64];
    wd[i] = dup2(v);
}

// ---------------- cur zero + ELL build ----------------
__global__ void zero_cur_k(int* __restrict__ p, int n)
{
    const int i = blockIdx.x * blockDim.x + threadIdx.x;
    if (i < n) p[i] = 0;
}

__global__ void ell_fill_k(const int* __restrict__ src, const int* __restrict__ dst,
                           int* __restrict__ cur, int* __restrict__ ell, int E)
{
    const int e = blockIdx.x * blockDim.x + threadIdx.x;
    if (e < E) {
        const int d = dst[e];
        const int pos = atomicAdd(cur + d, 1);
        if (pos < ELLW) ell[(size_t)d * ELLW + pos] = src[e];
    }
}

// ---------------- GEMM: out[N, 128] = act((act_in(in)+inbias) @ W + bias) ----------------
// Weights come PRE-DUPLICATED from global (ull = {w,w}) -> FFMA2 operand directly,
// no weight smem, no dup movs. SMEM holds only the 32KB x-tile -> 3 blocks/SM.
// SPLIT: cols [0,64) -> outa/biasa, [64,128) -> outb/biasb (width 64 each).
// DUAL:  blockIdx.y==1 swaps to (wdB, biasb, outb), full 128 cols.
template<bool SPLIT, bool GIN, bool GOUT, bool DUAL>
__global__ void __launch_bounds__(256, 3) gemm4_k(
    const float* __restrict__ in,
    const ull* __restrict__ wd, const ull* __restrict__ wdB,
    const float* __restrict__ biasa, const float* __restrict__ biasb,
    const float* __restrict__ inbias,
    float* __restrict__ outa, float* __restrict__ outb,
    int nrows)
{
    constexpr int COLS = 128;
    constexpr int HALF = 64;
    constexpr int PPG  = 8;            // row pairs per thread (4 groups x 8 = 32 pairs)
    __shared__ float xs[32 * 128 * 2]; // pairs: [32][128] f32x2 = 32KB
    const int tid  = threadIdx.x;
    const int row0 = blockIdx.x * 64;

    if (DUAL && blockIdx.y == 1) {
        wd = wdB; biasa = biasb; outa = outb;
    }

    // ---- activation tile: pair (r2,k) = {rowA[k], rowB[k]} ----
    {
        const float4* in4 = (const float4*)in;
        float4* xsf4 = (float4*)xs;
        for (int idx = tid; idx < 32 * 32; idx += 256) {
            const int r2 = idx >> 5;
            const int c4 = idx & 31;
            const int rA = row0 + 2 * r2, rB = rA + 1;
            float4 a = make_float4(0.f, 0.f, 0.f, 0.f);
            float4 b = make_float4(0.f, 0.f, 0.f, 0.f);
            if (rA < nrows) a = in4[(size_t)rA * 32 + c4];
            if (rB < nrows) b = in4[(size_t)rB * 32 + c4];
            if (GIN) {
                float4 bb = ((const float4*)inbias)[c4];
                a.x = gelu_erf(a.x + bb.x); a.y = gelu_erf(a.y + bb.y);
                a.z = gelu_erf(a.z + bb.z); a.w = gelu_erf(a.w + bb.w);
                b.x = gelu_erf(b.x + bb.x); b.y = gelu_erf(b.y + bb.y);
                b.z = gelu_erf(b.z + bb.z); b.w = gelu_erf(b.w + bb.w);
            }
            xsf4[r2 * 64 + 2 * c4]     = make_float4(a.x, b.x, a.y, b.y);
            xsf4[r2 * 64 + 2 * c4 + 1] = make_float4(a.z, b.z, a.w, b.w);
        }
    }
    __syncthreads();

    const int c0   = tid % HALF;
    const int grp  = tid / HALF;
    const int pr0  = grp * PPG;

    const float bA = biasa[c0];
    const float bB = SPLIT ? biasb[c0] : biasa[c0 + HALF];

    ull accA[PPG], accB[PPG];
    #pragma unroll
    for (int j = 0; j < PPG; j++) { accA[j] = dup2(bA); accB[j] = dup2(bB); }

    const ulonglong2* xsU2 = (const ulonglong2*)xs;
    const ull* wr = wd + c0;

    #pragma unroll 1
    for (int k4 = 0; k4 < 32; k4++) {
        const ull* wk = wr + 4 * k4 * COLS;
        const ull wA0 = __ldg(wk),            wA1 = __ldg(wk + COLS);
        const ull wA2 = __ldg(wk + 2 * COLS), wA3 = __ldg(wk + 3 * COLS);
        const ull wB0 = __ldg(wk + HALF),            wB1 = __ldg(wk + COLS + HALF);
        const ull wB2 = __ldg(wk + 2 * COLS + HALF), wB3 = __ldg(wk + 3 * COLS + HALF);
        #pragma unroll
        for (int j = 0; j < PPG; j++) {
            const ulonglong2 u0 = xsU2[(pr0 + j) * 64 + 2 * k4];
            const ulonglong2 u1 = xsU2[(pr0 + j) * 64 + 2 * k4 + 1];
            ull a = accA[j];
            a = ffma2(u0.x, wA0, a);
            a = ffma2(u0.y, wA1, a);
            a = ffma2(u1.x, wA2, a);
            a = ffma2(u1.y, wA3, a);
            accA[j] = a;
            ull b = accB[j];
            b = ffma2(u0.x, wB0, b);
            b = ffma2(u0.y, wB1, b);
            b = ffma2(u1.x, wB2, b);
            b = ffma2(u1.y, wB3, b);
            accB[j] = b;
        }
    }

    #pragma unroll
    for (int j = 0; j < PPG; j++) {
        float aA, aB, bAo, bBo;
        unpack2(accA[j], aA, aB);   // col c0: rowA, rowB
        unpack2(accB[j], bAo, bBo); // col c0+64
        if (GOUT) { aA = gelu_erf(aA); aB = gelu_erf(aB); bAo = gelu_erf(bAo); bBo = gelu_erf(bBo); }
        const int rA = row0 + 2 * (pr0 + j), rB = rA + 1;
        if (SPLIT) {
            if (rA < nrows) { outa[(size_t)rA * HALF + c0] = aA; outb[(size_t)rA * HALF + c0] = bAo; }
            if (rB < nrows) { outa[(size_t)rB * HALF + c0] = aB; outb[(size_t)rB * HALF + c0] = bBo; }
        } else {
            if (rA < nrows) { outa[(size_t)rA * COLS + c0] = aA; outa[(size_t)rA * COLS + c0 + HALF] = bAo; }
            if (rB < nrows) { outa[(size_t)rB * COLS + c0] = aB; outa[(size_t)rB * COLS + c0 + HALF] = bBo; }
        }
    }
}

// ---------------- fused GAT pull: warp per dst node, packed f32x2 math ----------------
// lrelu(v) = 0.6v + 0.4|v|; a pre-scaled by {0.6,0.4}*log2(e) so score -> ex2 directly.
template<int D, bool BIAS>
__global__ void __launch_bounds__(256) gat_pull_k(
    const float* __restrict__ q, const float* __restrict__ p,
    const float* __restrict__ a,
    const int* __restrict__ degp, const int* __restrict__ ell,
    const float* __restrict__ outbias,
    float* __restrict__ out, int N)
{
    constexpr int VC2 = D / 64;
    constexpr ull ABSM = 0x7FFFFFFF7FFFFFFFULL;
    constexpr float C6 = 0.6f * 1.4426950408889634f;
    constexpr float C4 = 0.4f * 1.4426950408889634f;
    const int w    = (int)((blockIdx.x * (unsigned)blockDim.x + threadIdx.x) >> 5);
    const int lane = threadIdx.x & 31;
    if (w >= N) return;

    ull q2[VC2], a6[VC2], a4[VC2], acc2[VC2];
    if (VC2 == 2) {
        const ulonglong2 t = ((const ulonglong2*)q)[(size_t)w * 32 + lane];
        q2[0] = t.x; q2[1] = t.y;
        const float4 u = ((const float4*)a)[lane];
        a6[0] = pack2(u.x * C6, u.y * C6); a6[1] = pack2(u.z * C6, u.w * C6);
        a4[0] = pack2(u.x * C4, u.y * C4); a4[1] = pack2(u.z * C4, u.w * C4);
    } else {
        q2[0] = ((const ull*)q)[(size_t)w * 32 + lane];
        const float2 u = ((const float2*)a)[lane];
        a6[0] = pack2(u.x * C6, u.y * C6);
        a4[0] = pack2(u.x * C4, u.y * C4);
    }
    #pragma unroll
    for (int i = 0; i < VC2; i++) acc2[i] = 0ULL;

    const int num = min(degp[w], ELLW);
    const int* rowp = ell + (size_t)w * ELLW;
    float den = 0.f;

    for (int base = 0; base < num; base += 32) {
        const int cnt = min(32, num - base);
        const int sl = (base + lane < num) ? rowp[base + lane] : 0;

        ull pv0[VC2], pv1[VC2], pn0[VC2], pn1[VC2];
        {
            const int s0 = __shfl_sync(0xffffffffu, sl, 0);
            const int s1 = __shfl_sync(0xffffffffu, sl, min(1, cnt - 1));
            if (VC2 == 2) {
                ulonglong2 t0 = ((const ulonglong2*)p)[(size_t)s0 * 32 + lane];
                pv0[0] = t0.x; pv0[1] = t0.y;
                ulonglong2 t1 = ((const ulonglong2*)p)[(size_t)s1 * 32 + lane];
                pv1[0] = t1.x; pv1[1] = t1.y;
            } else {
                pv0[0] = ((const ull*)p)[(size_t)s0 * 32 + lane];
                pv1[0] = ((const ull*)p)[(size_t)s1 * 32 + lane];
            }
        }

        for (int j = 0; j < cnt; j += 2) {
            {
                const int sA = __shfl_sync(0xffffffffu, sl, min(j + 2, cnt - 1));
                const int sB = __shfl_sync(0xffffffffu, sl, min(j + 3, cnt - 1));
                if (VC2 == 2) {
                    ulonglong2 tA = ((const ulonglong2*)p)[(size_t)sA * 32 + lane];
                    pn0[0] = tA.x; pn0[1] = tA.y;
                    ulonglong2 tB = ((const ulonglong2*)p)[(size_t)sB * 32 + lane];
                    pn1[0] = tB.x; pn1[1] = tB.y;
                } else {
                    pn0[0] = ((const ull*)p)[(size_t)sA * 32 + lane];
                    pn1[0] = ((const ull*)p)[(size_t)sB * 32 + lane];
                }
            }
            ull part0 = 0ULL, part1 = 0ULL;
            #pragma unroll
            for (int i = 0; i < VC2; i++) {
                const ull v0 = add2(q2[i], pv0[i]);
                part0 = ffma2(v0, a6[i], part0);
                part0 = ffma2(v0 & ABSM, a4[i], part0);
                const ull v1 = add2(q2[i], pv1[i]);
                part1 = ffma2(v1, a6[i], part1);
                part1 = ffma2(v1 & ABSM, a4[i], part1);
            }
            float s0lo, s0hi, s1lo, s1hi;
            unpack2(part0, s0lo, s0hi);
            unpack2(part1, s1lo, s1hi);
            float sc0 = s0lo + s0hi;
            float sc1 = s1lo + s1hi;
            #pragma unroll
            for (int off = 16; off; off >>= 1) {
                sc0 += __shfl_xor_sync(0xffffffffu, sc0, off);
                sc1 += __shfl_xor_sync(0xffffffffu, sc1, off);
            }
            const float ev0 = ex2f(sc0);
            const float ev1 = (j + 1 < cnt) ? ex2f(sc1) : 0.f;
            den += ev0 + ev1;
            const ull e0d = dup2(ev0);
            const ull e1d = dup2(ev1);
            #pragma unroll
            for (int i = 0; i < VC2; i++) {
                acc2[i] = ffma2(e0d, pv0[i], acc2[i]);
                acc2[i] = ffma2(e1d, pv1[i], acc2[i]);
                pv0[i] = pn0[i];
                pv1[i] = pn1[i];
            }
        }
    }

    const float inv = (num > 0) ? (1.f / den) : 0.f;
    if (VC2 == 2) {
        float o0, o1, o2, o3;
        unpack2(acc2[0], o0, o1);
        unpack2(acc2[1], o2, o3);
        float4 o = make_float4(o0 * inv, o1 * inv, o2 * inv, o3 * inv);
        if (BIAS) {
            float4 b = ((const float4*)outbias)[lane];
            o.x += b.x; o.y += b.y; o.z += b.z; o.w += b.w;
        }
        ((float4*)out)[(size_t)w * 32 + lane] = o;
    } else {
        float o0, o1;
        unpack2(acc2[0], o0, o1);
        float2 o = make_float2(o0 * inv, o1 * inv);
        if (BIAS) {
            float2 b = ((const float2*)outbias)[lane];
            o.x += b.x; o.y += b.y;
        }
        ((float2*)out)[(size_t)w * 32 + lane] = o;
    }
}

extern "C" void kernel_launch(void* const* d_in, const int* in_sizes, int n_in,
                              void* d_out, int out_size)
{
    const float* x    = (const float*)d_in[0];
    const float* W0   = (const float*)d_in[1];
    const float* b0   = (const float*)d_in[2];
    const float* Wq1  = (const float*)d_in[3];
    const float* bq1  = (const float*)d_in[4];
    const float* Wp1  = (const float*)d_in[5];
    const float* bp1  = (const float*)d_in[6];
    const float* a1   = (const float*)d_in[7];
    const float* bg2  = (const float*)d_in[8];
    const float* Wq2  = (const float*)d_in[9];
    const float* bq2  = (const float*)d_in[10];
    const float* Wp2  = (const float*)d_in[11];
    const float* bp2  = (const float*)d_in[12];
    const float* a2   = (const float*)d_in[13];
    const float* bout = (const float*)d_in[14];
    const int*   src  = (const int*)d_in[15];
    const int*   dst  = (const int*)d_in[16];
    const int E = in_sizes[15];
    const int N = in_sizes[0] / 128;
    float* out = (float*)d_out;

    float *m1p, *q1p, *p1p, *agg1p, *q2p, *p2p;
    int *curp, *ellp;
    ull *wdp;
    cudaGetSymbolAddress((void**)&m1p,   g_m1);
    cudaGetSymbolAddress((void**)&q1p,   g_q1);
    cudaGetSymbolAddress((void**)&p1p,   g_p1);
    cudaGetSymbolAddress((void**)&agg1p, g_agg1);
    cudaGetSymbolAddress((void**)&q2p,   g_q2);
    cudaGetSymbolAddress((void**)&p2p,   g_p2);
    cudaGetSymbolAddress((void**)&curp,  g_cur);
    cudaGetSymbolAddress((void**)&ellp,  g_ell);
    cudaGetSymbolAddress((void**)&wdp,   g_wd);

    const int gb = (N + 63) / 64;
    const int pullb = (N * 32 + 255) / 256;

    // ---- weight prepack + cur zero ----
    prep_w_k<<<256, 256>>>(W0, Wq1, Wp1, Wq2, Wp2, wdp);                 // launch 0
    zero_cur_k<<<(N + 255) / 256, 256>>>(curp, N);                       // launch 1

    // ---- Layer 0: m1 = gelu(x @ W0 + b0) ----
    gemm4_k<false, false, true, false><<<gb, 256>>>(                     // launch 2
        x, wdp, nullptr, b0, nullptr, nullptr, m1p, nullptr, N);

    // ---- Layer 1 GEMM: q1 (y=0), p1 (y=1) ----
    gemm4_k<false, false, false, true><<<dim3(gb, 2), 256>>>(            // launch 3 (profiled)
        m1p, wdp + 16384, wdp + 2 * 16384, bq1, bp1, nullptr, q1p, p1p, N);

    // ---- ELL build (by dst), shared by both layers ----
    ell_fill_k<<<(E + 255) / 256, 256>>>(src, dst, curp, ellp, E);       // launch 4

    // ---- Layer 1 pull ----
    gat_pull_k<128, false><<<pullb, 256>>>(                              // launch 5
        q1p, p1p, a1, curp, ellp, nullptr, agg1p, N);

    // ---- Layer 2 GAT ----
    gemm4_k<true, true, false, false><<<gb, 256>>>(                      // launch 6
        agg1p, wdp + 3 * 16384, nullptr, bq2, bp2, bg2, q2p, p2p, N);
    gat_pull_k<64, true><<<pullb, 256>>>(                                // launch 7
        q2p, p2p, a2, curp, ellp, bout, out, N);
}

// round 10
// speedup vs baseline: 1.4369x; 1.4369x over previous
#include <cuda_runtime.h>
#include <cuda_bf16.h>
#include <cstdint>
#include <math.h>

#define NMAX 50000
#define EMAX 800000
#define ELLW 64   // padded ELL width (max in-degree; Poisson(16) -> P(>=64) ~ 0)

typedef unsigned long long ull;
typedef unsigned char u8;
typedef unsigned int u32;

// ---------------- scratch (static device globals; no allocation) ----------------
__device__ u8    g_xh  [NMAX * 128 * 2];   // x bf16 hi
__device__ u8    g_xl  [NMAX * 128 * 2];   // x bf16 lo
__device__ u8    g_m1h [NMAX * 128 * 2];   // gelu(x@W0+b0) bf16 hi
__device__ u8    g_m1l [NMAX * 128 * 2];
__device__ u8    g_m2h [NMAX * 128 * 2];   // gelu(agg1+bg2) bf16 hi
__device__ u8    g_m2l [NMAX * 128 * 2];
__device__ float g_q1  [NMAX * 128];
__device__ float g_p1  [NMAX * 128];
__device__ float g_q2  [NMAX * 64];
__device__ float g_p2  [NMAX * 64];
__device__ int   g_cur [NMAX];
__device__ int   g_ell [NMAX * ELLW];
// 8 weight panels (64 cols x 128 k, Wt[n][k] bf16, 272B row pad): [hi 17408][lo 17408]
#define PANEL_SZ 34816
__device__ u8    g_wimg[8 * PANEL_SZ];

__device__ __forceinline__ float gelu_erf(float x) {
    return 0.5f * x * (1.0f + erff(x * 0.7071067811865476f));
}

// packed fp32x2 helpers (pull kernels)
__device__ __forceinline__ ull ffma2(ull a, ull b, ull c) {
    ull d;
    asm("fma.rn.f32x2 %0, %1, %2, %3;" : "=l"(d) : "l"(a), "l"(b), "l"(c));
    return d;
}
__device__ __forceinline__ ull add2(ull a, ull b) {
    ull d;
    asm("add.rn.f32x2 %0, %1, %2;" : "=l"(d) : "l"(a), "l"(b));
    return d;
}
__device__ __forceinline__ ull dup2(float w) {
    ull d;
    asm("mov.b64 %0, {%1, %1};" : "=l"(d) : "f"(w));
    return d;
}
__device__ __forceinline__ ull pack2(float lo, float hi) {
    ull d;
    asm("mov.b64 %0, {%1, %2};" : "=l"(d) : "f"(lo), "f"(hi));
    return d;
}
__device__ __forceinline__ void unpack2(ull v, float& lo, float& hi) {
    asm("mov.b64 {%0, %1}, %2;" : "=f"(lo), "=f"(hi) : "l"(v));
}
__device__ __forceinline__ float ex2f(float x) {
    float r;
    asm("ex2.approx.ftz.f32 %0, %1;" : "=f"(r) : "f"(x));
    return r;
}

__device__ __forceinline__ u32 smem_u32(const void* p) {
    u32 a;
    asm("{ .reg .u64 t; cvta.to.shared.u64 t, %1; cvt.u32.u64 %0, t; }" : "=r"(a) : "l"(p));
    return a;
}

// ldmatrix x4 (non-trans)
__device__ __forceinline__ void ldm4(u32& r0, u32& r1, u32& r2, u32& r3, u32 addr) {
    asm volatile("ldmatrix.sync.aligned.m8n8.x4.shared.b16 {%0,%1,%2,%3}, [%4];"
                 : "=r"(r0), "=r"(r1), "=r"(r2), "=r"(r3) : "r"(addr));
}
// m16n8k16 bf16 mma, fp32 accum
__device__ __forceinline__ void mma16816(float* d, const u32* a, u32 b0, u32 b1) {
    asm volatile("mma.sync.aligned.m16n8k16.row.col.f32.bf16.bf16.f32 "
                 "{%0,%1,%2,%3}, {%4,%5,%6,%7}, {%8,%9}, {%0,%1,%2,%3};"
                 : "+f"(d[0]), "+f"(d[1]), "+f"(d[2]), "+f"(d[3])
                 : "r"(a[0]), "r"(a[1]), "r"(a[2]), "r"(a[3]), "r"(b0), "r"(b1));
}

__device__ __forceinline__ void split_bf16(float v, __nv_bfloat16& h, __nv_bfloat16& l) {
    h = __float2bfloat16(v);
    l = __float2bfloat16(v - __bfloat162float(h));
}

// ---------------- prep: 8 weight panels (Wt[n][k] hi/lo) + cur zero ----------------
__global__ void prep_k(const float* __restrict__ W0,
                       const float* __restrict__ Wq1, const float* __restrict__ Wp1,
                       const float* __restrict__ Wq2, const float* __restrict__ Wp2,
                       u8* __restrict__ img, int* __restrict__ cur, int nnodes)
{
    const int i = blockIdx.x * blockDim.x + threadIdx.x;   // 0..65535
    if (i < nnodes) cur[i] = 0;
    const int p = i >> 13;          // panel 0..7
    const int idx = i & 8191;
    const int n = idx >> 7, k = idx & 127;
    float v;
    switch (p) {
        case 0: v = W0 [k * 128 + n];        break;
        case 1: v = W0 [k * 128 + 64 + n];   break;
        case 2: v = Wq1[k * 128 + n];        break;
        case 3: v = Wq1[k * 128 + 64 + n];   break;
        case 4: v = Wp1[k * 128 + n];        break;
        case 5: v = Wp1[k * 128 + 64 + n];   break;
        case 6: v = Wq2[k * 64 + n];         break;
        default: v = Wp2[k * 64 + n];        break;
    }
    __nv_bfloat16 h, l;
    split_bf16(v, h, l);
    u8* base = img + p * PANEL_SZ + n * 272 + k * 2;
    *(__nv_bfloat16*)(base)         = h;
    *(__nv_bfloat16*)(base + 17408) = l;
}

// ---------------- conv_x: x fp32 -> bf16 hi/lo ----------------
__global__ void conv_x_k(const float* __restrict__ x, u8* __restrict__ xh, u8* __restrict__ xl, int n4)
{
    const int i = blockIdx.x * blockDim.x + threadIdx.x;   // over N*32
    if (i >= n4) return;
    const float4 v = ((const float4*)x)[i];
    __nv_bfloat16 h0, h1, h2, h3, l0, l1, l2, l3;
    split_bf16(v.x, h0, l0); split_bf16(v.y, h1, l1);
    split_bf16(v.z, h2, l2); split_bf16(v.w, h3, l3);
    __nv_bfloat162 ph0 = __nv_bfloat162(h0, h1), ph1 = __nv_bfloat162(h2, h3);
    __nv_bfloat162 pl0 = __nv_bfloat162(l0, l1), pl1 = __nv_bfloat162(l2, l3);
    uint2 uh, ul;
    uh.x = *(u32*)&ph0; uh.y = *(u32*)&ph1;
    ul.x = *(u32*)&pl0; ul.y = *(u32*)&pl1;
    ((uint2*)xh)[i] = uh;
    ((uint2*)xl)[i] = ul;
}

// ---------------- ELL build ----------------
__global__ void ell_fill_k(const int* __restrict__ src, const int* __restrict__ dst,
                           int* __restrict__ cur, int* __restrict__ ell, int E)
{
    const int e = blockIdx.x * blockDim.x + threadIdx.x;
    if (e < E) {
        const int d = dst[e];
        const int pos = atomicAdd(cur + d, 1);
        if (pos < ELLW) ell[(size_t)d * ELLW + pos] = src[e];
    }
}

// ---------------- mma.sync GEMM: 128 rows x 64 cols x K=128 per block ----------------
// A (bf16 hi/lo, [N][128] global) @ W panel y -> out cols [64*idx, 64*idx+64).
// bf16x3: D = Ah*Wh + Ah*Wl + Al*Wh. EPIBF: gelu + split into (outA=hi, outB=lo) bf16,
// else fp32 to (y<S ? outA : outB).
#define OFF_BIAS 0
#define OFF_AH   512
#define OFF_AL   (512 + 34816)
#define OFF_WH   (512 + 2 * 34816)
#define OFF_WL   (512 + 2 * 34816 + 17408)
#define GSMEM_SZ (512 + 2 * 34816 + 2 * 17408)

template<bool EPIBF>
__global__ void __launch_bounds__(256) mma_gemm_k(
    const u8* __restrict__ Ah, const u8* __restrict__ Al,
    const u8* __restrict__ img,
    const float* __restrict__ bias0, const float* __restrict__ bias1,
    void* outA, void* outB,
    int S, int ostride, int nrows)
{
    extern __shared__ char smem[];
    const u32 sb = smem_u32(smem);
    const int tid = threadIdx.x;
    const int wid = tid >> 5;
    const int lane = tid & 31;
    const int row0 = blockIdx.x * 128;
    const int y = blockIdx.y;
    const int idx = (y < S) ? y : y - S;
    const int col0 = 64 * idx;
    const float* bias = ((y < S) ? bias0 : bias1) + 64 * idx;
    float* fout = (float*)((y < S) ? outA : outB);

    // bias
    if (tid < 64) *(float*)(smem + OFF_BIAS + tid * 4) = bias[tid];

    // W panel copy (already in final layout): hi+lo = 2176 x 16B
    {
        const uint4* s = (const uint4*)(img + (size_t)y * PANEL_SZ);
        uint4* d = (uint4*)(smem + OFF_WH);
        #pragma unroll
        for (int i = tid; i < 2176; i += 256) d[i] = s[i];
    }
    // A copy: 128 rows x 16 chunks x {hi,lo}
    {
        const uint4* sh = (const uint4*)Ah;
        const uint4* sl = (const uint4*)Al;
        for (int c = tid; c < 2048; c += 256) {
            const int r = c >> 4, cc = c & 15;
            int row = row0 + r;
            if (row >= nrows) row = nrows - 1;
            const uint4 vh = sh[(size_t)row * 16 + cc];
            const uint4 vl = sl[(size_t)row * 16 + cc];
            *(uint4*)(smem + OFF_AH + r * 272 + cc * 16) = vh;
            *(uint4*)(smem + OFF_AL + r * 272 + cc * 16) = vl;
        }
    }
    __syncthreads();

    const int wm = (wid & 3) * 32;   // warp row base
    const int wn = (wid >> 2) * 32;  // warp col base
    const int g   = lane >> 2;
    const int tig = lane & 3;

    // accumulators init from bias
    float acc[2][4][4];
    #pragma unroll
    for (int nt = 0; nt < 4; nt++) {
        const float2 bv = *(const float2*)(smem + OFF_BIAS + (wn + nt * 8 + 2 * tig) * 4);
        #pragma unroll
        for (int mt = 0; mt < 2; mt++) {
            acc[mt][nt][0] = bv.x; acc[mt][nt][1] = bv.y;
            acc[mt][nt][2] = bv.x; acc[mt][nt][3] = bv.y;
        }
    }

    // ldmatrix base addresses
    const u32 aOff = (u32)((wm + (lane & 15)) * 272 + ((lane >> 4) << 4));
    const u32 aH = sb + OFF_AH + aOff;
    const u32 aL = sb + OFF_AL + aOff;
    const u32 bOff = (u32)((wn + (lane & 7) + ((lane >> 4) << 3)) * 272 + (((lane >> 3) & 1) << 4));
    const u32 bH = sb + OFF_WH + bOff;
    const u32 bL = sb + OFF_WL + bOff;

    #pragma unroll 1
    for (int s = 0; s < 8; s++) {
        const u32 ko = s * 32;
        u32 ah[2][4], al[2][4], bh[2][4], bl[2][4];
        ldm4(ah[0][0], ah[0][1], ah[0][2], ah[0][3], aH + ko);
        ldm4(ah[1][0], ah[1][1], ah[1][2], ah[1][3], aH + ko + 16 * 272);
        ldm4(al[0][0], al[0][1], al[0][2], al[0][3], aL + ko);
        ldm4(al[1][0], al[1][1], al[1][2], al[1][3], aL + ko + 16 * 272);
        ldm4(bh[0][0], bh[0][1], bh[0][2], bh[0][3], bH + ko);          // tiles 0,1
        ldm4(bh[1][0], bh[1][1], bh[1][2], bh[1][3], bH + ko + 16 * 272); // tiles 2,3
        ldm4(bl[0][0], bl[0][1], bl[0][2], bl[0][3], bL + ko);
        ldm4(bl[1][0], bl[1][1], bl[1][2], bl[1][3], bL + ko + 16 * 272);
        #pragma unroll
        for (int mt = 0; mt < 2; mt++) {
            #pragma unroll
            for (int nt = 0; nt < 4; nt++) {
                const int pr = nt >> 1, h = (nt & 1) * 2;
                mma16816(acc[mt][nt], ah[mt], bh[pr][h], bh[pr][h + 1]);
                mma16816(acc[mt][nt], ah[mt], bl[pr][h], bl[pr][h + 1]);
                mma16816(acc[mt][nt], al[mt], bh[pr][h], bh[pr][h + 1]);
            }
        }
    }

    // epilogue
    #pragma unroll
    for (int mt = 0; mt < 2; mt++) {
        #pragma unroll
        for (int nt = 0; nt < 4; nt++) {
            const int r1 = row0 + wm + mt * 16 + g;
            const int r2 = r1 + 8;
            const int col = col0 + wn + nt * 8 + 2 * tig;
            float d0 = acc[mt][nt][0], d1 = acc[mt][nt][1];
            float d2 = acc[mt][nt][2], d3 = acc[mt][nt][3];
            if (EPIBF) {
                d0 = gelu_erf(d0); d1 = gelu_erf(d1);
                d2 = gelu_erf(d2); d3 = gelu_erf(d3);
                __nv_bfloat16 h0, h1, h2, h3, l0, l1, l2, l3;
                split_bf16(d0, h0, l0); split_bf16(d1, h1, l1);
                split_bf16(d2, h2, l2); split_bf16(d3, h3, l3);
                u8* oh = (u8*)outA; u8* ol = (u8*)outB;
                if (r1 < nrows) {
                    __nv_bfloat162 ph = __nv_bfloat162(h0, h1), pl = __nv_bfloat162(l0, l1);
                    *(u32*)(oh + ((size_t)r1 * 128 + col) * 2) = *(u32*)&ph;
                    *(u32*)(ol + ((size_t)r1 * 128 + col) * 2) = *(u32*)&pl;
                }
                if (r2 < nrows) {
                    __nv_bfloat162 ph = __nv_bfloat162(h2, h3), pl = __nv_bfloat162(l2, l3);
                    *(u32*)(oh + ((size_t)r2 * 128 + col) * 2) = *(u32*)&ph;
                    *(u32*)(ol + ((size_t)r2 * 128 + col) * 2) = *(u32*)&pl;
                }
            } else {
                if (r1 < nrows) *(float2*)(fout + (size_t)r1 * ostride + col) = make_float2(d0, d1);
                if (r2 < nrows) *(float2*)(fout + (size_t)r2 * ostride + col) = make_float2(d2, d3);
            }
        }
    }
}

// ---------------- fused GAT pull: warp per dst node, packed f32x2 math ----------------
// M2OUT: epilogue writes gelu(acc/den + inbias) split to bf16 hi/lo (m2h/m2l).
template<int D, bool BIAS, bool M2OUT>
__global__ void __launch_bounds__(256) gat_pull_k(
    const float* __restrict__ q, const float* __restrict__ p,
    const float* __restrict__ a,
    const int* __restrict__ degp, const int* __restrict__ ell,
    const float* __restrict__ outbias,
    float* __restrict__ out, u8* __restrict__ outh, u8* __restrict__ outl, int N)
{
    constexpr int VC2 = D / 64;
    constexpr ull ABSM = 0x7FFFFFFF7FFFFFFFULL;
    constexpr float C6 = 0.6f * 1.4426950408889634f;
    constexpr float C4 = 0.4f * 1.4426950408889634f;
    const int w    = (int)((blockIdx.x * (unsigned)blockDim.x + threadIdx.x) >> 5);
    const int lane = threadIdx.x & 31;
    if (w >= N) return;

    ull q2[VC2], a6[VC2], a4[VC2], acc2[VC2];
    if (VC2 == 2) {
        const ulonglong2 t = ((const ulonglong2*)q)[(size_t)w * 32 + lane];
        q2[0] = t.x; q2[1] = t.y;
        const float4 u = ((const float4*)a)[lane];
        a6[0] = pack2(u.x * C6, u.y * C6); a6[1] = pack2(u.z * C6, u.w * C6);
        a4[0] = pack2(u.x * C4, u.y * C4); a4[1] = pack2(u.z * C4, u.w * C4);
    } else {
        q2[0] = ((const ull*)q)[(size_t)w * 32 + lane];
        const float2 u = ((const float2*)a)[lane];
        a6[0] = pack2(u.x * C6, u.y * C6);
        a4[0] = pack2(u.x * C4, u.y * C4);
    }
    #pragma unroll
    for (int i = 0; i < VC2; i++) acc2[i] = 0ULL;

    const int num = min(degp[w], ELLW);
    const int* rowp = ell + (size_t)w * ELLW;
    float den = 0.f;

    for (int base = 0; base < num; base += 32) {
        const int cnt = min(32, num - base);
        const int sl = (base + lane < num) ? rowp[base + lane] : 0;

        ull pv0[VC2], pv1[VC2], pn0[VC2], pn1[VC2];
        {
            const int s0 = __shfl_sync(0xffffffffu, sl, 0);
            const int s1 = __shfl_sync(0xffffffffu, sl, min(1, cnt - 1));
            if (VC2 == 2) {
                ulonglong2 t0 = ((const ulonglong2*)p)[(size_t)s0 * 32 + lane];
                pv0[0] = t0.x; pv0[1] = t0.y;
                ulonglong2 t1 = ((const ulonglong2*)p)[(size_t)s1 * 32 + lane];
                pv1[0] = t1.x; pv1[1] = t1.y;
            } else {
                pv0[0] = ((const ull*)p)[(size_t)s0 * 32 + lane];
                pv1[0] = ((const ull*)p)[(size_t)s1 * 32 + lane];
            }
        }

        for (int j = 0; j < cnt; j += 2) {
            {
                const int sA = __shfl_sync(0xffffffffu, sl, min(j + 2, cnt - 1));
                const int sB = __shfl_sync(0xffffffffu, sl, min(j + 3, cnt - 1));
                if (VC2 == 2) {
                    ulonglong2 tA = ((const ulonglong2*)p)[(size_t)sA * 32 + lane];
                    pn0[0] = tA.x; pn0[1] = tA.y;
                    ulonglong2 tB = ((const ulonglong2*)p)[(size_t)sB * 32 + lane];
                    pn1[0] = tB.x; pn1[1] = tB.y;
                } else {
                    pn0[0] = ((const ull*)p)[(size_t)sA * 32 + lane];
                    pn1[0] = ((const ull*)p)[(size_t)sB * 32 + lane];
                }
            }
            ull part0 = 0ULL, part1 = 0ULL;
            #pragma unroll
            for (int i = 0; i < VC2; i++) {
                const ull v0 = add2(q2[i], pv0[i]);
                part0 = ffma2(v0, a6[i], part0);
                part0 = ffma2(v0 & ABSM, a4[i], part0);
                const ull v1 = add2(q2[i], pv1[i]);
                part1 = ffma2(v1, a6[i], part1);
                part1 = ffma2(v1 & ABSM, a4[i], part1);
            }
            float s0lo, s0hi, s1lo, s1hi;
            unpack2(part0, s0lo, s0hi);
            unpack2(part1, s1lo, s1hi);
            float sc0 = s0lo + s0hi;
            float sc1 = s1lo + s1hi;
            #pragma unroll
            for (int off = 16; off; off >>= 1) {
                sc0 += __shfl_xor_sync(0xffffffffu, sc0, off);
                sc1 += __shfl_xor_sync(0xffffffffu, sc1, off);
            }
            const float ev0 = ex2f(sc0);
            const float ev1 = (j + 1 < cnt) ? ex2f(sc1) : 0.f;
            den += ev0 + ev1;
            const ull e0d = dup2(ev0);
            const ull e1d = dup2(ev1);
            #pragma unroll
            for (int i = 0; i < VC2; i++) {
                acc2[i] = ffma2(e0d, pv0[i], acc2[i]);
                acc2[i] = ffma2(e1d, pv1[i], acc2[i]);
                pv0[i] = pn0[i];
                pv1[i] = pn1[i];
            }
        }
    }

    const float inv = (num > 0) ? (1.f / den) : 0.f;
    if (VC2 == 2) {
        float o0, o1, o2, o3;
        unpack2(acc2[0], o0, o1);
        unpack2(acc2[1], o2, o3);
        o0 *= inv; o1 *= inv; o2 *= inv; o3 *= inv;
        if (M2OUT) {
            const float4 b = ((const float4*)outbias)[lane];   // bg2
            o0 = gelu_erf(o0 + b.x); o1 = gelu_erf(o1 + b.y);
            o2 = gelu_erf(o2 + b.z); o3 = gelu_erf(o3 + b.w);
            __nv_bfloat16 h0, h1, h2, h3, l0, l1, l2, l3;
            split_bf16(o0, h0, l0); split_bf16(o1, h1, l1);
            split_bf16(o2, h2, l2); split_bf16(o3, h3, l3);
            __nv_bfloat162 ph0 = __nv_bfloat162(h0, h1), ph1 = __nv_bfloat162(h2, h3);
            __nv_bfloat162 pl0 = __nv_bfloat162(l0, l1), pl1 = __nv_bfloat162(l2, l3);
            uint2 uh, ul2;
            uh.x = *(u32*)&ph0; uh.y = *(u32*)&ph1;
            ul2.x = *(u32*)&pl0; ul2.y = *(u32*)&pl1;
            ((uint2*)outh)[(size_t)w * 32 + lane] = uh;
            ((uint2*)outl)[(size_t)w * 32 + lane] = ul2;
        } else {
            float4 o = make_float4(o0, o1, o2, o3);
            if (BIAS) {
                const float4 b = ((const float4*)outbias)[lane];
                o.x += b.x; o.y += b.y; o.z += b.z; o.w += b.w;
            }
            ((float4*)out)[(size_t)w * 32 + lane] = o;
        }
    } else {
        float o0, o1;
        unpack2(acc2[0], o0, o1);
        float2 o = make_float2(o0 * inv, o1 * inv);
        if (BIAS) {
            const float2 b = ((const float2*)outbias)[lane];
            o.x += b.x; o.y += b.y;
        }
        ((float2*)out)[(size_t)w * 32 + lane] = o;
    }
}

extern "C" void kernel_launch(void* const* d_in, const int* in_sizes, int n_in,
                              void* d_out, int out_size)
{
    const float* x    = (const float*)d_in[0];
    const float* W0   = (const float*)d_in[1];
    const float* b0   = (const float*)d_in[2];
    const float* Wq1  = (const float*)d_in[3];
    const float* bq1  = (const float*)d_in[4];
    const float* Wp1  = (const float*)d_in[5];
    const float* bp1  = (const float*)d_in[6];
    const float* a1   = (const float*)d_in[7];
    const float* bg2  = (const float*)d_in[8];
    const float* Wq2  = (const float*)d_in[9];
    const float* bq2  = (const float*)d_in[10];
    const float* Wp2  = (const float*)d_in[11];
    const float* bp2  = (const float*)d_in[12];
    const float* a2   = (const float*)d_in[13];
    const float* bout = (const float*)d_in[14];
    const int*   src  = (const int*)d_in[15];
    const int*   dst  = (const int*)d_in[16];
    const int E = in_sizes[15];
    const int N = in_sizes[0] / 128;
    float* out = (float*)d_out;

    u8 *xh, *xl, *m1h, *m1l, *m2h, *m2l, *wimg;
    float *q1p, *p1p, *q2p, *p2p;
    int *curp, *ellp;
    cudaGetSymbolAddress((void**)&xh,   g_xh);
    cudaGetSymbolAddress((void**)&xl,   g_xl);
    cudaGetSymbolAddress((void**)&m1h,  g_m1h);
    cudaGetSymbolAddress((void**)&m1l,  g_m1l);
    cudaGetSymbolAddress((void**)&m2h,  g_m2h);
    cudaGetSymbolAddress((void**)&m2l,  g_m2l);
    cudaGetSymbolAddress((void**)&q1p,  g_q1);
    cudaGetSymbolAddress((void**)&p1p,  g_p1);
    cudaGetSymbolAddress((void**)&q2p,  g_q2);
    cudaGetSymbolAddress((void**)&p2p,  g_p2);
    cudaGetSymbolAddress((void**)&curp, g_cur);
    cudaGetSymbolAddress((void**)&ellp, g_ell);
    cudaGetSymbolAddress((void**)&wimg, g_wimg);

    cudaFuncSetAttribute(mma_gemm_k<true>,
                         cudaFuncAttributeMaxDynamicSharedMemorySize, GSMEM_SZ);
    cudaFuncSetAttribute(mma_gemm_k<false>,
                         cudaFuncAttributeMaxDynamicSharedMemorySize, GSMEM_SZ);

    const int gb = (N + 127) / 128;
    const int pullb = (N * 32 + 255) / 256;

    // 0: weight panels + cur zero
    prep_k<<<256, 256>>>(W0, Wq1, Wp1, Wq2, Wp2, wimg, curp, N);
    // 1: x -> bf16 hi/lo
    conv_x_k<<<(N * 32 + 255) / 256, 256>>>(x, xh, xl, N * 32);
    // 2: layer 0 GEMM: m1 = gelu(x @ W0 + b0) -> bf16 hi/lo
    mma_gemm_k<true><<<dim3(gb, 2), 256, GSMEM_SZ>>>(
        xh, xl, wimg, b0, nullptr, m1h, m1l, 2, 128, N);
    // 3 (profiled): layer 1 GEMM: q1 (y=0,1), p1 (y=2,3)
    mma_gemm_k<false><<<dim3(gb, 4), 256, GSMEM_SZ>>>(
        m1h, m1l, wimg + 2 * PANEL_SZ, bq1, bp1, q1p, p1p, 2, 128, N);
    // 4: ELL build
    ell_fill_k<<<(E + 255) / 256, 256>>>(src, dst, curp, ellp, E);
    // 5: layer 1 pull -> m2 = gelu(agg + bg2) bf16 hi/lo
    gat_pull_k<128, false, true><<<pullb, 256>>>(
        q1p, p1p, a1, curp, ellp, bg2, nullptr, m2h, m2l, N);
    // 6: layer 2 GEMM: q2 (y=0), p2 (y=1)
    mma_gemm_k<false><<<dim3(gb, 2), 256, GSMEM_SZ>>>(
        m2h, m2l, wimg + 6 * PANEL_SZ, bq2, bp2, q2p, p2p, 1, 64, N);
    // 7: layer 2 pull -> out
    gat_pull_k<64, true, false><<<pullb, 256>>>(
        q2p, p2p, a2, curp, ellp, bout, out, nullptr, nullptr, N);
}